// round 5
// baseline (speedup 1.0000x reference)
#include <cuda_runtime.h>
#include <cuda_bf16.h>
#include <math.h>
#include <stdint.h>

#define N_RAYS   4096
#define PSTEPS   254
#define P_INNER  231
#define MTOT     (N_RAYS*PSTEPS)      // 1,040,384
#define NTILES   (MTOT/128)           // 8128
#define WORLD    160
#define S2       (WORLD*WORLD)
#define S3       (WORLD*WORLD*WORLD)
#define ACT_SHIFT (-9.210240371976183f)
#define BG_LEN   0.2f
#define GRID_MLP 296                  // 2 CTAs per SM

// ---------------- scratch ----------------
__device__ uint16_t g_fhi[MTOT*16];     // k0 features bf16-hi rows (12 real + 4 pad)
__device__ uint16_t g_flo[MTOT*16];     // residual (lo) rows
__device__ float    g_vembf[N_RAYS*27]; // view embedding fp32
__device__ float    g_h0v[N_RAYS*128];  // per-ray layer0 contribution of vemb + b0
__device__ float    g_alpha[MTOT];
__device__ float    g_w[MTOT];

// ---------------- helpers ----------------
__device__ __forceinline__ uint16_t f2bf(float f) {
    return __bfloat16_as_ushort(__float2bfloat16(f));
}
__device__ __forceinline__ float bf2f(uint16_t u) {
    return __bfloat162float(__ushort_as_bfloat16(u));
}
__device__ __forceinline__ uint32_t pack_bf2(float f0, float f1) {   // f0 -> low half
    __nv_bfloat162 v = __floats2bfloat162_rn(f0, f1);
    return *reinterpret_cast<uint32_t*>(&v);
}
__device__ __forceinline__ uint32_t smem_u32(const void* p) {
    uint32_t a;
    asm("{ .reg .u64 t; cvta.to.shared.u64 t, %1; cvt.u32.u64 %0, t; }" : "=r"(a) : "l"(p));
    return a;
}

#define LDSM_X4(r0,r1,r2,r3,addr) \
    asm volatile("ldmatrix.sync.aligned.m8n8.x4.shared.b16 {%0,%1,%2,%3}, [%4];" \
        : "=r"(r0), "=r"(r1), "=r"(r2), "=r"(r3) : "r"(addr))

#define MMA_BF16(c, a0,a1,a2,a3, b0,b1) \
    asm volatile("mma.sync.aligned.m16n8k16.row.col.f32.bf16.bf16.f32 " \
        "{%0,%1,%2,%3}, {%4,%5,%6,%7}, {%8,%9}, {%0,%1,%2,%3};" \
        : "+f"((c)[0]), "+f"((c)[1]), "+f"((c)[2]), "+f"((c)[3]) \
        : "r"(a0), "r"(a1), "r"(a2), "r"(a3), "r"(b0), "r"(b1))

// ---------------- K1: sampling + contraction + trilinear interp ----------------
__global__ void k_sample(const float* __restrict__ ro, const float* __restrict__ rdir,
                         const float* __restrict__ dgrid, const float* __restrict__ k0g,
                         const int* __restrict__ stepsize)
{
    int s = blockIdx.x * blockDim.x + threadIdx.x;
    if (s >= MTOT) return;
    int r = s / PSTEPS;
    int p = s - r * PSTEPS;

    const float SQ3x2 = 3.4641016151377546f;
    float t;
    if (p < P_INNER) {
        t = SQ3x2 * ((float)p + 0.5f) * (1.0f / 231.0f);
    } else {
        int q = p - P_INNER;
        float L0 = 1.0f - (float)q     * (0.999f / 23.0f);
        float L1 = 1.0f - (float)(q+1) * (0.999f / 23.0f);
        t = 0.5f * SQ3x2 * (1.0f / L0 + 1.0f / L1);
    }

    float dx = rdir[r*3+0], dy = rdir[r*3+1], dz = rdir[r*3+2];
    float inv = rsqrtf(dx*dx + dy*dy + dz*dz);
    dx *= inv; dy *= inv; dz *= inv;

    float px = ro[r*3+0] + dx * t;
    float py = ro[r*3+1] + dy * t;
    float pz = ro[r*3+2] + dz * t;

    float nm = fmaxf(fabsf(px), fmaxf(fabsf(py), fabsf(pz)));
    if (nm > 1.0f) {
        float sc = (1.0f + BG_LEN - BG_LEN / nm) / nm;
        px *= sc; py *= sc; pz *= sc;
    }

    const float GS = 159.0f / 2.4f;
    float gx = fminf(fmaxf((px + 1.2f) * GS, 0.0f), 159.0f);
    float gy = fminf(fmaxf((py + 1.2f) * GS, 0.0f), 159.0f);
    float gz = fminf(fmaxf((pz + 1.2f) * GS, 0.0f), 159.0f);
    int ix = min((int)gx, 158);
    int iy = min((int)gy, 158);
    int iz = min((int)gz, 158);
    float fx = gx - (float)ix, fy = gy - (float)iy, fz = gz - (float)iz;

    int base = (ix * WORLD + iy) * WORLD + iz;
    float w00 = (1.f-fx)*(1.f-fy), w01 = (1.f-fx)*fy, w10 = fx*(1.f-fy), w11 = fx*fy;
    float wz0 = 1.f - fz, wz1 = fz;

    float wt[8];
    wt[0]=w00*wz0; wt[1]=w00*wz1; wt[2]=w01*wz0; wt[3]=w01*wz1;
    wt[4]=w10*wz0; wt[5]=w10*wz1; wt[6]=w11*wz0; wt[7]=w11*wz1;
    int off[8];
    off[0]=base;          off[1]=base+1;
    off[2]=base+WORLD;    off[3]=base+WORLD+1;
    off[4]=base+S2;       off[5]=base+S2+1;
    off[6]=base+S2+WORLD; off[7]=base+S2+WORLD+1;

    float dsum = 0.0f;
    #pragma unroll
    for (int u = 0; u < 8; u++) dsum += wt[u] * __ldg(&dgrid[off[u]]);

    int sv = *stepsize;
    float interval = (sv > 0 && sv < 1000000) ? (float)sv : __int_as_float(sv);

    float x = dsum + ACT_SHIFT;
    float sp = (x > 20.0f) ? x : log1pf(expf(x));
    g_alpha[s] = 1.0f - expf(-interval * sp);

    // k0 channels -> bf16 hi/lo packed rows (12 values + 4 zero pad)
    float v[12];
    #pragma unroll
    for (int c = 0; c < 12; c++) {
        const float* gp = k0g + c * S3;
        float acc = 0.0f;
        #pragma unroll
        for (int u = 0; u < 8; u++) acc += wt[u] * __ldg(&gp[off[u]]);
        v[c] = acc;
    }
    uint32_t phi[8], plo[8];
    #pragma unroll
    for (int c = 0; c < 6; c++) {
        float a = v[2*c], b = v[2*c+1];
        uint32_t h = pack_bf2(a, b);
        phi[c] = h;
        float ha = __uint_as_float(h << 16);
        float hb = __uint_as_float(h & 0xffff0000u);
        plo[c] = pack_bf2(a - ha, b - hb);
    }
    phi[6]=phi[7]=plo[6]=plo[7]=0u;
    uint4* dh = (uint4*)&g_fhi[(size_t)s*16];
    uint4* dl = (uint4*)&g_flo[(size_t)s*16];
    dh[0] = make_uint4(phi[0],phi[1],phi[2],phi[3]);
    dh[1] = make_uint4(phi[4],phi[5],phi[6],phi[7]);
    dl[0] = make_uint4(plo[0],plo[1],plo[2],plo[3]);
    dl[1] = make_uint4(plo[4],plo[5],plo[6],plo[7]);
}

// ---------------- K2: warp-parallel view embedding + transmittance scan ----------------
__global__ void k_scan(const float* __restrict__ vdirs, float* __restrict__ out)
{
    int gw = (blockIdx.x * blockDim.x + threadIdx.x) >> 5;   // ray id
    int lane = threadIdx.x & 31;
    if (gw >= N_RAYS) return;

    float d0 = __ldg(&vdirs[gw*3+0]);
    float d1 = __ldg(&vdirs[gw*3+1]);
    float d2 = __ldg(&vdirs[gw*3+2]);

    if (lane < 27) {
        float v;
        if (lane < 3) {
            v = (lane == 0) ? d0 : (lane == 1) ? d1 : d2;
        } else {
            int kk = (lane < 15) ? (lane - 3) : (lane - 15);
            int c = kk >> 2, e = kk & 3;
            float dc = (c == 0) ? d0 : (c == 1) ? d1 : d2;
            float vv = dc * (float)(1 << e);
            v = (lane < 15) ? sinf(vv) : cosf(vv);
        }
        g_vembf[gw*27 + lane] = v;
    }

    float T = 1.0f;
    int base = gw * PSTEPS;
    #pragma unroll
    for (int chunk = 0; chunk < 8; chunk++) {
        int p = chunk*32 + lane;
        float a = (p < PSTEPS) ? g_alpha[base + p] : 0.0f;
        float q = 1.0f - a;
        float incl = q;
        #pragma unroll
        for (int dlt = 1; dlt < 32; dlt <<= 1) {
            float o = __shfl_up_sync(0xffffffffu, incl, dlt);
            if (lane >= dlt) incl *= o;
        }
        float excl = __shfl_up_sync(0xffffffffu, incl, 1);
        if (lane == 0) excl = 1.0f;
        if (p < PSTEPS) g_w[base + p] = a * T * excl;
        float tot = __shfl_sync(0xffffffffu, incl, 31);
        T *= tot;
    }
    if (lane == 0) {
        out[gw*3+0] = T; out[gw*3+1] = T; out[gw*3+2] = T;   // BG = 1.0
    }
}

// ---------------- K2b: per-ray layer0 view contribution: h0v = b0 + vemb @ W0[12:39] ----------------
__global__ void k_h0v(const float* __restrict__ w0, const float* __restrict__ b0)
{
    int gid = blockIdx.x * blockDim.x + threadIdx.x;
    int r = gid >> 7, n = gid & 127;
    float acc = __ldg(&b0[n]);
    #pragma unroll
    for (int k = 0; k < 27; k++)
        acc = fmaf(g_vembf[r*27 + k], __ldg(&w0[(12+k)*128 + n]), acc);
    g_h0v[r*128 + n] = acc;
}

// ---------------- K3: persistent mma.sync MLP, 128 threads, M=32/warp, 2 CTAs/SM ----------------
// smem layout (bytes)
#define SM_B1V   0                     // 128 floats
#define SM_W2    512                   // 384 floats
#define SM_A0    2048                  // double buffer: [buf][hi/lo][128 rows][24 bf16] = 2*2*6144
#define SM_B0H   26624                 // [128 n][24 k] stride 48B
#define SM_B0L   32768
#define SM_B1H   38912                 // [128 n][136 k] stride 272B
#define SM_B1L   73728
#define SMEM_TOTAL 108544

__global__ void __launch_bounds__(128, 2) k_mlp(
    const float* __restrict__ w0, const float* __restrict__ b0,
    const float* __restrict__ w1, const float* __restrict__ b1,
    const float* __restrict__ w2, const float* __restrict__ b2,
    float* __restrict__ out)
{
    extern __shared__ unsigned char smem[];
    uint32_t sb = smem_u32(smem);
    int tid = threadIdx.x;
    int w = tid >> 5, l = tid & 31;
    int g = l >> 2, tg = l & 3;

    // ---- one-time weight staging (bf16 hi/lo, [n][k] layout) ----
    if (tid < 128) ((float*)(smem + SM_B1V))[tid] = b1[tid];
    for (int i = tid; i < 384; i += 128) ((float*)(smem + SM_W2))[i] = w2[i];

    for (int idx = tid; idx < 128*16; idx += 128) {
        int n = idx & 127, k = idx >> 7;
        float v = (k < 12) ? w0[k*128 + n] : 0.0f;
        uint16_t h = f2bf(v);
        uint16_t lo16 = f2bf(v - bf2f(h));
        *(uint16_t*)(smem + SM_B0H + n*48 + k*2) = h;
        *(uint16_t*)(smem + SM_B0L + n*48 + k*2) = lo16;
    }
    for (int idx = tid; idx < 128*128; idx += 128) {
        int n = idx & 127, k = idx >> 7;
        float v = w1[k*128 + n];
        uint16_t h = f2bf(v);
        uint16_t lo16 = f2bf(v - bf2f(h));
        *(uint16_t*)(smem + SM_B1H + n*272 + k*2) = h;
        *(uint16_t*)(smem + SM_B1L + n*272 + k*2) = lo16;
    }
    float b2r0 = __ldg(&b2[0]), b2r1 = __ldg(&b2[1]), b2r2 = __ldg(&b2[2]);
    const float* b1s = (const float*)(smem + SM_B1V);
    const float* w2s = (const float*)(smem + SM_W2);

    // ---- lane-invariant ldmatrix addresses ----
    uint32_t rowA = 32u*w + (l & 7) + ((l >> 3) & 1) * 8;     // block 0; block 1 = +16 rows
    uint32_t colA = (uint32_t)(l >> 4) * 16;
    uint32_t lrow = (l & 7) + ((l >> 4) & 1) * 8;
    uint32_t lcol = ((l >> 3) & 1) * 16;
    uint32_t aB0H = sb + SM_B0H + lrow*48  + lcol;
    uint32_t aB0L = sb + SM_B0L + lrow*48  + lcol;
    uint32_t aB1H = sb + SM_B1H + lrow*272 + lcol;
    uint32_t aB1L = sb + SM_B1L + lrow*272 + lcol;

    int srow = tid;   // 0..127: each thread stages one row, hi AND lo

    // ---- prime A0 buffer 0 ----
    int m = blockIdx.x;
    if (m < NTILES) {
        const uint4* sh = (const uint4*)&g_fhi[(size_t)(m*128+srow)*16];
        const uint4* sl = (const uint4*)&g_flo[(size_t)(m*128+srow)*16];
        uint4 h0 = sh[0], h1 = sh[1], l0 = sl[0], l1 = sl[1];
        *(uint4*)(smem + SM_A0 + srow*48)           = h0;
        *(uint4*)(smem + SM_A0 + srow*48 + 16)      = h1;
        *(uint4*)(smem + SM_A0 + 6144 + srow*48)      = l0;
        *(uint4*)(smem + SM_A0 + 6144 + srow*48 + 16) = l1;
    }
    __syncthreads();
    int buf = 0;

    for (; m < NTILES; m += gridDim.x) {
        int mbase = m * 128;
        int mn = m + gridDim.x;
        bool hn = mn < NTILES;
        uint4 qh0n, qh1n, ql0n, ql1n;
        if (hn) {   // prefetch next tile rows (hidden under compute)
            const uint4* sh = (const uint4*)&g_fhi[(size_t)(mn*128+srow)*16];
            const uint4* sl = (const uint4*)&g_flo[(size_t)(mn*128+srow)*16];
            qh0n = sh[0]; qh1n = sh[1]; ql0n = sl[0]; ql1n = sl[1];
        }

        // sample ids: [block][rowhalf]
        int s00 = mbase + 32*w + g;        // block0 rows g, g+8
        int s01 = s00 + 8;
        int s10 = s00 + 16;                // block1
        int s11 = s00 + 24;
        int r00 = s00 / PSTEPS, r01 = s01 / PSTEPS;
        int r10 = s10 / PSTEPS, r11 = s11 / PSTEPS;
        const float* hp[2][2] = {
            { g_h0v + (size_t)r00*128, g_h0v + (size_t)r01*128 },
            { g_h0v + (size_t)r10*128, g_h0v + (size_t)r11*128 } };

        // ---- layer 0: K=16, fused epilogue per 16-col chunk -> A1 frags ----
        uint32_t aA = sb + SM_A0 + (uint32_t)buf*12288u + rowA*48 + colA;
        uint32_t aH0[2][4], aL0[2][4];
        LDSM_X4(aH0[0][0],aH0[0][1],aH0[0][2],aH0[0][3], aA);
        LDSM_X4(aH0[1][0],aH0[1][1],aH0[1][2],aH0[1][3], aA + 768);
        LDSM_X4(aL0[0][0],aL0[0][1],aL0[0][2],aL0[0][3], aA + 6144);
        LDSM_X4(aL0[1][0],aL0[1][1],aL0[1][2],aL0[1][3], aA + 6144 + 768);

        uint32_t aH1[2][8][4], aL1[2][8][4];
        #pragma unroll
        for (int p = 0; p < 8; p++) {
            float cc[2][2][4];
            #pragma unroll
            for (int b = 0; b < 2; b++)
                #pragma unroll
                for (int hh = 0; hh < 2; hh++)
                    cc[b][hh][0]=cc[b][hh][1]=cc[b][hh][2]=cc[b][hh][3]=0.f;
            uint32_t bh0,bh1,bh2,bh3, bl0,bl1,bl2,bl3;
            LDSM_X4(bh0,bh1,bh2,bh3, aB0H + p*768);
            LDSM_X4(bl0,bl1,bl2,bl3, aB0L + p*768);
            #pragma unroll
            for (int b = 0; b < 2; b++) {
                MMA_BF16(cc[b][0], aH0[b][0],aH0[b][1],aH0[b][2],aH0[b][3], bh0,bh1);
                MMA_BF16(cc[b][1], aH0[b][0],aH0[b][1],aH0[b][2],aH0[b][3], bh2,bh3);
                MMA_BF16(cc[b][0], aH0[b][0],aH0[b][1],aH0[b][2],aH0[b][3], bl0,bl1);
                MMA_BF16(cc[b][1], aH0[b][0],aH0[b][1],aH0[b][2],aH0[b][3], bl2,bl3);
                MMA_BF16(cc[b][0], aL0[b][0],aL0[b][1],aL0[b][2],aL0[b][3], bh0,bh1);
                MMA_BF16(cc[b][1], aL0[b][0],aL0[b][1],aL0[b][2],aL0[b][3], bh2,bh3);
            }
            #pragma unroll
            for (int b = 0; b < 2; b++)
                #pragma unroll
                for (int hh = 0; hh < 2; hh++) {
                    const float* c4 = cc[b][hh];
                    int col = p*16 + hh*8 + tg*2;
                    float f00 = fmaxf(c4[0] + hp[b][0][col],   0.f);
                    float f01 = fmaxf(c4[1] + hp[b][0][col+1], 0.f);
                    float f10 = fmaxf(c4[2] + hp[b][1][col],   0.f);
                    float f11 = fmaxf(c4[3] + hp[b][1][col+1], 0.f);
                    uint32_t pk0 = pack_bf2(f00, f01);
                    uint32_t pk1 = pack_bf2(f10, f11);
                    aH1[b][p][0+hh*2] = pk0;
                    aH1[b][p][1+hh*2] = pk1;
                    aL1[b][p][0+hh*2] = pack_bf2(f00 - __uint_as_float(pk0 << 16),
                                                 f01 - __uint_as_float(pk0 & 0xffff0000u));
                    aL1[b][p][1+hh*2] = pack_bf2(f10 - __uint_as_float(pk1 << 16),
                                                 f11 - __uint_as_float(pk1 & 0xffff0000u));
                }
        }

        // ---- layer 1: K=128, fused epilogue per 16-col chunk -> w2 partials ----
        float acc[2][2][3];
        #pragma unroll
        for (int b = 0; b < 2; b++)
            #pragma unroll
            for (int hh = 0; hh < 2; hh++)
                acc[b][hh][0]=acc[b][hh][1]=acc[b][hh][2]=0.f;

        #pragma unroll
        for (int p = 0; p < 8; p++) {
            float cc[2][2][4];
            #pragma unroll
            for (int b = 0; b < 2; b++)
                #pragma unroll
                for (int hh = 0; hh < 2; hh++)
                    cc[b][hh][0]=cc[b][hh][1]=cc[b][hh][2]=cc[b][hh][3]=0.f;
            #pragma unroll
            for (int ks = 0; ks < 8; ks++) {
                uint32_t bh0,bh1,bh2,bh3, bl0,bl1,bl2,bl3;
                LDSM_X4(bh0,bh1,bh2,bh3, aB1H + p*4352 + ks*32);
                LDSM_X4(bl0,bl1,bl2,bl3, aB1L + p*4352 + ks*32);
                #pragma unroll
                for (int b = 0; b < 2; b++) {
                    MMA_BF16(cc[b][0], aH1[b][ks][0],aH1[b][ks][1],aH1[b][ks][2],aH1[b][ks][3], bh0,bh1);
                    MMA_BF16(cc[b][1], aH1[b][ks][0],aH1[b][ks][1],aH1[b][ks][2],aH1[b][ks][3], bh2,bh3);
                    MMA_BF16(cc[b][0], aH1[b][ks][0],aH1[b][ks][1],aH1[b][ks][2],aH1[b][ks][3], bl0,bl1);
                    MMA_BF16(cc[b][1], aH1[b][ks][0],aH1[b][ks][1],aH1[b][ks][2],aH1[b][ks][3], bl2,bl3);
                    MMA_BF16(cc[b][0], aL1[b][ks][0],aL1[b][ks][1],aL1[b][ks][2],aL1[b][ks][3], bh0,bh1);
                    MMA_BF16(cc[b][1], aL1[b][ks][0],aL1[b][ks][1],aL1[b][ks][2],aL1[b][ks][3], bh2,bh3);
                }
            }
            #pragma unroll
            for (int b = 0; b < 2; b++)
                #pragma unroll
                for (int hh = 0; hh < 2; hh++) {
                    const float* c4 = cc[b][hh];
                    int col = p*16 + hh*8 + tg*2;
                    float f0 = fmaxf(c4[0] + b1s[col],   0.f);
                    float f1 = fmaxf(c4[1] + b1s[col+1], 0.f);
                    float f2 = fmaxf(c4[2] + b1s[col],   0.f);
                    float f3 = fmaxf(c4[3] + b1s[col+1], 0.f);
                    float wa0 = w2s[col*3+0],     wa1 = w2s[col*3+1],     wa2 = w2s[col*3+2];
                    float wb0 = w2s[(col+1)*3+0], wb1 = w2s[(col+1)*3+1], wb2 = w2s[(col+1)*3+2];
                    acc[b][0][0] = fmaf(f0, wa0, fmaf(f1, wb0, acc[b][0][0]));
                    acc[b][0][1] = fmaf(f0, wa1, fmaf(f1, wb1, acc[b][0][1]));
                    acc[b][0][2] = fmaf(f0, wa2, fmaf(f1, wb2, acc[b][0][2]));
                    acc[b][1][0] = fmaf(f2, wa0, fmaf(f3, wb0, acc[b][1][0]));
                    acc[b][1][1] = fmaf(f2, wa1, fmaf(f3, wb1, acc[b][1][1]));
                    acc[b][1][2] = fmaf(f2, wa2, fmaf(f3, wb2, acc[b][1][2]));
                }
        }

        // ---- quad reduce + sigmoid + weighted atomic (4 samples per quad) ----
        #pragma unroll
        for (int dlt = 1; dlt <= 2; dlt <<= 1)
            #pragma unroll
            for (int b = 0; b < 2; b++)
                #pragma unroll
                for (int hh = 0; hh < 2; hh++) {
                    acc[b][hh][0] += __shfl_xor_sync(0xffffffffu, acc[b][hh][0], dlt);
                    acc[b][hh][1] += __shfl_xor_sync(0xffffffffu, acc[b][hh][1], dlt);
                    acc[b][hh][2] += __shfl_xor_sync(0xffffffffu, acc[b][hh][2], dlt);
                }
        if (tg == 0) {
            int ss[2][2] = {{s00, s01}, {s10, s11}};
            int rr[2][2] = {{r00, r01}, {r10, r11}};
            #pragma unroll
            for (int b = 0; b < 2; b++)
                #pragma unroll
                for (int hh = 0; hh < 2; hh++) {
                    float wg = g_w[ss[b][hh]];
                    float v0 = wg / (1.0f + expf(-(acc[b][hh][0] + b2r0)));
                    float v1 = wg / (1.0f + expf(-(acc[b][hh][1] + b2r1)));
                    float v2 = wg / (1.0f + expf(-(acc[b][hh][2] + b2r2)));
                    atomicAdd(&out[rr[b][hh]*3+0], v0);
                    atomicAdd(&out[rr[b][hh]*3+1], v1);
                    atomicAdd(&out[rr[b][hh]*3+2], v2);
                }
        }

        // ---- stage next tile into alternate buffer ----
        if (hn) {
            uint32_t ab = SM_A0 + (uint32_t)(buf^1)*12288u;
            *(uint4*)(smem + ab + srow*48)             = qh0n;
            *(uint4*)(smem + ab + srow*48 + 16)        = qh1n;
            *(uint4*)(smem + ab + 6144 + srow*48)      = ql0n;
            *(uint4*)(smem + ab + 6144 + srow*48 + 16) = ql1n;
        }
        __syncthreads();
        buf ^= 1;
    }
}

// ---------------- launcher ----------------
extern "C" void kernel_launch(void* const* d_in, const int* in_sizes, int n_in,
                              void* d_out, int out_size)
{
    const float* rays_o   = (const float*)d_in[0];
    const float* rays_d   = (const float*)d_in[1];
    const float* viewdirs = (const float*)d_in[2];
    const float* dgrid    = (const float*)d_in[3];
    const float* k0g      = (const float*)d_in[4];
    const float* w0 = (const float*)d_in[5];
    const float* b0 = (const float*)d_in[6];
    const float* w1 = (const float*)d_in[7];
    const float* b1 = (const float*)d_in[8];
    const float* w2 = (const float*)d_in[9];
    const float* b2 = (const float*)d_in[10];
    const int* stepsize = (const int*)d_in[11];
    float* out = (float*)d_out;

    cudaFuncSetAttribute(k_mlp, cudaFuncAttributeMaxDynamicSharedMemorySize, SMEM_TOTAL);

    k_sample<<<(MTOT + 255) / 256, 256>>>(rays_o, rays_d, dgrid, k0g, stepsize);
    k_scan<<<(N_RAYS * 32 + 255) / 256, 256>>>(viewdirs, out);
    k_h0v<<<(N_RAYS * 128) / 256, 256>>>(w0, b0);
    k_mlp<<<GRID_MLP, 128, SMEM_TOTAL>>>(w0, b0, w1, b1, w2, b2, out);
}

// round 6
// speedup vs baseline: 1.4554x; 1.4554x over previous
#include <cuda_runtime.h>
#include <cuda_fp16.h>
#include <math.h>
#include <stdint.h>

#define N_RAYS   4096
#define PSTEPS   254
#define P_INNER  231
#define MTOT     (N_RAYS*PSTEPS)      // 1,040,384
#define NTILES   (MTOT/128)           // 8128
#define WORLD    160
#define S2       (WORLD*WORLD)
#define S3       (WORLD*WORLD*WORLD)
#define ACT_SHIFT (-9.210240371976183f)
#define BG_LEN   0.2f
#define GRID_MLP 296                  // 2 CTAs per SM

// ---------------- scratch ----------------
__device__ uint16_t g_f16[MTOT*16];     // k0 features fp16 rows (12 real + 4 pad)
__device__ float    g_vembf[N_RAYS*27]; // view embedding fp32
__device__ float    g_h0v[N_RAYS*128];  // per-ray layer0 contribution of vemb + b0
__device__ float    g_alpha[MTOT];
__device__ float    g_w[MTOT];

// ---------------- helpers ----------------
__device__ __forceinline__ uint16_t f2h(float f) {
    return __half_as_ushort(__float2half_rn(f));
}
__device__ __forceinline__ uint32_t pack_h2(float f0, float f1) {   // f0 -> low half
    __half2 v = __floats2half2_rn(f0, f1);
    return *reinterpret_cast<uint32_t*>(&v);
}
__device__ __forceinline__ uint32_t smem_u32(const void* p) {
    uint32_t a;
    asm("{ .reg .u64 t; cvta.to.shared.u64 t, %1; cvt.u32.u64 %0, t; }" : "=r"(a) : "l"(p));
    return a;
}

#define LDSM_X4(r0,r1,r2,r3,addr) \
    asm volatile("ldmatrix.sync.aligned.m8n8.x4.shared.b16 {%0,%1,%2,%3}, [%4];" \
        : "=r"(r0), "=r"(r1), "=r"(r2), "=r"(r3) : "r"(addr))

#define MMA_F16(c, a0,a1,a2,a3, b0,b1) \
    asm volatile("mma.sync.aligned.m16n8k16.row.col.f32.f16.f16.f32 " \
        "{%0,%1,%2,%3}, {%4,%5,%6,%7}, {%8,%9}, {%0,%1,%2,%3};" \
        : "+f"((c)[0]), "+f"((c)[1]), "+f"((c)[2]), "+f"((c)[3]) \
        : "r"(a0), "r"(a1), "r"(a2), "r"(a3), "r"(b0), "r"(b1))

// ---------------- K1: sampling + contraction + trilinear interp ----------------
__global__ void k_sample(const float* __restrict__ ro, const float* __restrict__ rdir,
                         const float* __restrict__ dgrid, const float* __restrict__ k0g,
                         const int* __restrict__ stepsize)
{
    int s = blockIdx.x * blockDim.x + threadIdx.x;
    if (s >= MTOT) return;
    int r = s / PSTEPS;
    int p = s - r * PSTEPS;

    const float SQ3x2 = 3.4641016151377546f;
    float t;
    if (p < P_INNER) {
        t = SQ3x2 * ((float)p + 0.5f) * (1.0f / 231.0f);
    } else {
        int q = p - P_INNER;
        float L0 = 1.0f - (float)q     * (0.999f / 23.0f);
        float L1 = 1.0f - (float)(q+1) * (0.999f / 23.0f);
        t = 0.5f * SQ3x2 * (1.0f / L0 + 1.0f / L1);
    }

    float dx = rdir[r*3+0], dy = rdir[r*3+1], dz = rdir[r*3+2];
    float inv = rsqrtf(dx*dx + dy*dy + dz*dz);
    dx *= inv; dy *= inv; dz *= inv;

    float px = ro[r*3+0] + dx * t;
    float py = ro[r*3+1] + dy * t;
    float pz = ro[r*3+2] + dz * t;

    float nm = fmaxf(fabsf(px), fmaxf(fabsf(py), fabsf(pz)));
    if (nm > 1.0f) {
        float sc = (1.0f + BG_LEN - BG_LEN / nm) / nm;
        px *= sc; py *= sc; pz *= sc;
    }

    const float GS = 159.0f / 2.4f;
    float gx = fminf(fmaxf((px + 1.2f) * GS, 0.0f), 159.0f);
    float gy = fminf(fmaxf((py + 1.2f) * GS, 0.0f), 159.0f);
    float gz = fminf(fmaxf((pz + 1.2f) * GS, 0.0f), 159.0f);
    int ix = min((int)gx, 158);
    int iy = min((int)gy, 158);
    int iz = min((int)gz, 158);
    float fx = gx - (float)ix, fy = gy - (float)iy, fz = gz - (float)iz;

    int base = (ix * WORLD + iy) * WORLD + iz;
    float w00 = (1.f-fx)*(1.f-fy), w01 = (1.f-fx)*fy, w10 = fx*(1.f-fy), w11 = fx*fy;
    float wz0 = 1.f - fz, wz1 = fz;

    float wt[8];
    wt[0]=w00*wz0; wt[1]=w00*wz1; wt[2]=w01*wz0; wt[3]=w01*wz1;
    wt[4]=w10*wz0; wt[5]=w10*wz1; wt[6]=w11*wz0; wt[7]=w11*wz1;
    int off[8];
    off[0]=base;          off[1]=base+1;
    off[2]=base+WORLD;    off[3]=base+WORLD+1;
    off[4]=base+S2;       off[5]=base+S2+1;
    off[6]=base+S2+WORLD; off[7]=base+S2+WORLD+1;

    float dsum = 0.0f;
    #pragma unroll
    for (int u = 0; u < 8; u++) dsum += wt[u] * __ldg(&dgrid[off[u]]);

    int sv = *stepsize;
    float interval = (sv > 0 && sv < 1000000) ? (float)sv : __int_as_float(sv);

    float x = dsum + ACT_SHIFT;
    float sp = (x > 20.0f) ? x : log1pf(expf(x));
    g_alpha[s] = 1.0f - expf(-interval * sp);

    // k0 channels -> fp16 packed rows (12 values + 4 zero pad)
    float v[12];
    #pragma unroll
    for (int c = 0; c < 12; c++) {
        const float* gp = k0g + c * S3;
        float acc = 0.0f;
        #pragma unroll
        for (int u = 0; u < 8; u++) acc += wt[u] * __ldg(&gp[off[u]]);
        v[c] = acc;
    }
    uint32_t ph[8];
    #pragma unroll
    for (int c = 0; c < 6; c++) ph[c] = pack_h2(v[2*c], v[2*c+1]);
    ph[6] = ph[7] = 0u;
    uint4* dh = (uint4*)&g_f16[(size_t)s*16];
    dh[0] = make_uint4(ph[0],ph[1],ph[2],ph[3]);
    dh[1] = make_uint4(ph[4],ph[5],ph[6],ph[7]);
}

// ---------------- K2: warp-parallel view embedding + transmittance scan ----------------
__global__ void k_scan(const float* __restrict__ vdirs, float* __restrict__ out)
{
    int gw = (blockIdx.x * blockDim.x + threadIdx.x) >> 5;   // ray id
    int lane = threadIdx.x & 31;
    if (gw >= N_RAYS) return;

    float d0 = __ldg(&vdirs[gw*3+0]);
    float d1 = __ldg(&vdirs[gw*3+1]);
    float d2 = __ldg(&vdirs[gw*3+2]);

    if (lane < 27) {
        float v;
        if (lane < 3) {
            v = (lane == 0) ? d0 : (lane == 1) ? d1 : d2;
        } else {
            int kk = (lane < 15) ? (lane - 3) : (lane - 15);
            int c = kk >> 2, e = kk & 3;
            float dc = (c == 0) ? d0 : (c == 1) ? d1 : d2;
            float vv = dc * (float)(1 << e);
            v = (lane < 15) ? sinf(vv) : cosf(vv);
        }
        g_vembf[gw*27 + lane] = v;
    }

    float T = 1.0f;
    int base = gw * PSTEPS;
    #pragma unroll
    for (int chunk = 0; chunk < 8; chunk++) {
        int p = chunk*32 + lane;
        float a = (p < PSTEPS) ? g_alpha[base + p] : 0.0f;
        float q = 1.0f - a;
        float incl = q;
        #pragma unroll
        for (int dlt = 1; dlt < 32; dlt <<= 1) {
            float o = __shfl_up_sync(0xffffffffu, incl, dlt);
            if (lane >= dlt) incl *= o;
        }
        float excl = __shfl_up_sync(0xffffffffu, incl, 1);
        if (lane == 0) excl = 1.0f;
        if (p < PSTEPS) g_w[base + p] = a * T * excl;
        float tot = __shfl_sync(0xffffffffu, incl, 31);
        T *= tot;
    }
    if (lane == 0) {
        out[gw*3+0] = T; out[gw*3+1] = T; out[gw*3+2] = T;   // BG = 1.0
    }
}

// ---------------- K2b: per-ray layer0 view contribution: h0v = b0 + vemb @ W0[12:39] ----------------
__global__ void k_h0v(const float* __restrict__ w0, const float* __restrict__ b0)
{
    int gid = blockIdx.x * blockDim.x + threadIdx.x;
    int r = gid >> 7, n = gid & 127;
    float acc = __ldg(&b0[n]);
    #pragma unroll
    for (int k = 0; k < 27; k++)
        acc = fmaf(g_vembf[r*27 + k], __ldg(&w0[(12+k)*128 + n]), acc);
    g_h0v[r*128 + n] = acc;
}

// ---------------- K3: persistent mma.sync fp16 MLP, 256 threads, 2 CTAs/SM ----------------
// smem layout (bytes)
#define SM_B1V   0                     // 128 floats
#define SM_W2    512                   // 384 floats
#define SM_A0    2048                  // double buffer: [buf][128 rows][24 fp16] = 2*6144
#define SM_B0    14336                 // [128 n][24 k] stride 48B (k 0..15 real)
#define SM_B1    20480                 // [128 n][136 k] stride 272B (k 0..127 real)
#define SMEM_TOTAL 55296

__global__ void __launch_bounds__(256, 2) k_mlp(
    const float* __restrict__ w0, const float* __restrict__ b0,
    const float* __restrict__ w1, const float* __restrict__ b1,
    const float* __restrict__ w2, const float* __restrict__ b2,
    float* __restrict__ out)
{
    extern __shared__ unsigned char smem[];
    uint32_t sb = smem_u32(smem);
    int tid = threadIdx.x;
    int w = tid >> 5, l = tid & 31;
    int g = l >> 2, tg = l & 3;

    // ---- one-time weight staging (fp16, [n][k] layout) ----
    if (tid < 128) ((float*)(smem + SM_B1V))[tid] = b1[tid];
    for (int i = tid; i < 384; i += 256) ((float*)(smem + SM_W2))[i] = w2[i];

    for (int idx = tid; idx < 128*16; idx += 256) {
        int n = idx & 127, k = idx >> 7;
        float v = (k < 12) ? w0[k*128 + n] : 0.0f;
        *(uint16_t*)(smem + SM_B0 + n*48 + k*2) = f2h(v);
    }
    for (int idx = tid; idx < 128*128; idx += 256) {
        int n = idx & 127, k = idx >> 7;
        *(uint16_t*)(smem + SM_B1 + n*272 + k*2) = f2h(w1[k*128 + n]);
    }
    float b2r0 = __ldg(&b2[0]), b2r1 = __ldg(&b2[1]), b2r2 = __ldg(&b2[2]);
    const float* b1s = (const float*)(smem + SM_B1V);
    const float* w2s = (const float*)(smem + SM_W2);

    // ---- lane-invariant ldmatrix addresses ----
    uint32_t rowA = 16u*w + (l & 7) + ((l >> 3) & 1) * 8;
    uint32_t colA = (uint32_t)(l >> 4) * 16;
    uint32_t lrow = (l & 7) + ((l >> 4) & 1) * 8;
    uint32_t lcol = ((l >> 3) & 1) * 16;
    uint32_t aB0 = sb + SM_B0 + lrow*48  + lcol;
    uint32_t aB1 = sb + SM_B1 + lrow*272 + lcol;

    int srow = tid & 127;
    uint32_t part = (tid < 128) ? 0u : 16u;    // which uint4 of the row this thread stages

    // ---- prime A0 buffer 0 ----
    int m = blockIdx.x;
    if (m < NTILES) {
        const uint4* sf = (const uint4*)&g_f16[(size_t)(m*128+srow)*16];
        uint4 q = sf[part >> 4];
        *(uint4*)(smem + SM_A0 + srow*48 + part) = q;
    }
    __syncthreads();
    int buf = 0;

    for (; m < NTILES; m += gridDim.x) {
        int mbase = m * 128;
        int mn = m + gridDim.x;
        bool hn = mn < NTILES;
        uint4 qn;
        if (hn) {   // prefetch next tile rows (hidden under compute)
            const uint4* sf = (const uint4*)&g_f16[(size_t)(mn*128+srow)*16];
            qn = sf[part >> 4];
        }

        int s0 = mbase + 16*w + g;
        int s1 = s0 + 8;
        int r0 = s0 / PSTEPS, r1 = s1 / PSTEPS;
        const float* h0p = g_h0v + (size_t)r0*128;
        const float* h1p = g_h0v + (size_t)r1*128;

        // ---- layer 0: K=16, fused epilogue per 16-col chunk -> A1 frags ----
        uint32_t aA0 = sb + SM_A0 + (uint32_t)buf*6144u + rowA*48 + colA;
        uint32_t a00,a01,a02,a03;
        LDSM_X4(a00,a01,a02,a03, aA0);

        uint32_t aF[8][4];
        #pragma unroll
        for (int p = 0; p < 8; p++) {
            float cc0[4] = {0.f,0.f,0.f,0.f}, cc1[4] = {0.f,0.f,0.f,0.f};
            uint32_t bb0,bb1,bb2,bb3;
            LDSM_X4(bb0,bb1,bb2,bb3, aB0 + p*768);
            MMA_F16(cc0, a00,a01,a02,a03, bb0,bb1);
            MMA_F16(cc1, a00,a01,a02,a03, bb2,bb3);
            #pragma unroll
            for (int hh = 0; hh < 2; hh++) {
                const float* c4 = hh ? cc1 : cc0;
                int col = p*16 + hh*8 + tg*2;
                float f00 = fmaxf(c4[0] + h0p[col],   0.f);
                float f01 = fmaxf(c4[1] + h0p[col+1], 0.f);
                float f10 = fmaxf(c4[2] + h1p[col],   0.f);
                float f11 = fmaxf(c4[3] + h1p[col+1], 0.f);
                aF[p][0+hh*2] = pack_h2(f00, f01);
                aF[p][1+hh*2] = pack_h2(f10, f11);
            }
        }

        // ---- layer 1: K=128, fused epilogue per 16-col chunk -> w2 partials ----
        float p00=0.f,p01=0.f,p02=0.f, p10=0.f,p11=0.f,p12=0.f;
        #pragma unroll
        for (int p = 0; p < 8; p++) {
            float cc0[4] = {0.f,0.f,0.f,0.f}, cc1[4] = {0.f,0.f,0.f,0.f};
            #pragma unroll
            for (int ks = 0; ks < 8; ks++) {
                uint32_t bb0,bb1,bb2,bb3;
                LDSM_X4(bb0,bb1,bb2,bb3, aB1 + p*4352 + ks*32);
                MMA_F16(cc0, aF[ks][0],aF[ks][1],aF[ks][2],aF[ks][3], bb0,bb1);
                MMA_F16(cc1, aF[ks][0],aF[ks][1],aF[ks][2],aF[ks][3], bb2,bb3);
            }
            #pragma unroll
            for (int hh = 0; hh < 2; hh++) {
                const float* c4 = hh ? cc1 : cc0;
                int col = p*16 + hh*8 + tg*2;
                float f0 = fmaxf(c4[0] + b1s[col],   0.f);
                float f1 = fmaxf(c4[1] + b1s[col+1], 0.f);
                float f2 = fmaxf(c4[2] + b1s[col],   0.f);
                float f3 = fmaxf(c4[3] + b1s[col+1], 0.f);
                float wa0 = w2s[col*3+0],     wa1 = w2s[col*3+1],     wa2 = w2s[col*3+2];
                float wb0 = w2s[(col+1)*3+0], wb1 = w2s[(col+1)*3+1], wb2 = w2s[(col+1)*3+2];
                p00 = fmaf(f0, wa0, fmaf(f1, wb0, p00));
                p01 = fmaf(f0, wa1, fmaf(f1, wb1, p01));
                p02 = fmaf(f0, wa2, fmaf(f1, wb2, p02));
                p10 = fmaf(f2, wa0, fmaf(f3, wb0, p10));
                p11 = fmaf(f2, wa1, fmaf(f3, wb1, p11));
                p12 = fmaf(f2, wa2, fmaf(f3, wb2, p12));
            }
        }

        // ---- quad reduce + sigmoid + weighted atomic ----
        #pragma unroll
        for (int dlt = 1; dlt <= 2; dlt <<= 1) {
            p00 += __shfl_xor_sync(0xffffffffu, p00, dlt);
            p01 += __shfl_xor_sync(0xffffffffu, p01, dlt);
            p02 += __shfl_xor_sync(0xffffffffu, p02, dlt);
            p10 += __shfl_xor_sync(0xffffffffu, p10, dlt);
            p11 += __shfl_xor_sync(0xffffffffu, p11, dlt);
            p12 += __shfl_xor_sync(0xffffffffu, p12, dlt);
        }
        if (tg == 0) {
            float wg0 = g_w[s0], wg1 = g_w[s1];
            float v00 = wg0 / (1.0f + expf(-(p00 + b2r0)));
            float v01 = wg0 / (1.0f + expf(-(p01 + b2r1)));
            float v02 = wg0 / (1.0f + expf(-(p02 + b2r2)));
            float v10 = wg1 / (1.0f + expf(-(p10 + b2r0)));
            float v11 = wg1 / (1.0f + expf(-(p11 + b2r1)));
            float v12 = wg1 / (1.0f + expf(-(p12 + b2r2)));
            atomicAdd(&out[r0*3+0], v00);
            atomicAdd(&out[r0*3+1], v01);
            atomicAdd(&out[r0*3+2], v02);
            atomicAdd(&out[r1*3+0], v10);
            atomicAdd(&out[r1*3+1], v11);
            atomicAdd(&out[r1*3+2], v12);
        }

        // ---- stage next tile into alternate buffer ----
        if (hn) {
            uint32_t ab = SM_A0 + (uint32_t)(buf^1)*6144u;
            *(uint4*)(smem + ab + srow*48 + part) = qn;
        }
        __syncthreads();
        buf ^= 1;
    }
}

// ---------------- launcher ----------------
extern "C" void kernel_launch(void* const* d_in, const int* in_sizes, int n_in,
                              void* d_out, int out_size)
{
    const float* rays_o   = (const float*)d_in[0];
    const float* rays_d   = (const float*)d_in[1];
    const float* viewdirs = (const float*)d_in[2];
    const float* dgrid    = (const float*)d_in[3];
    const float* k0g      = (const float*)d_in[4];
    const float* w0 = (const float*)d_in[5];
    const float* b0 = (const float*)d_in[6];
    const float* w1 = (const float*)d_in[7];
    const float* b1 = (const float*)d_in[8];
    const float* w2 = (const float*)d_in[9];
    const float* b2 = (const float*)d_in[10];
    const int* stepsize = (const int*)d_in[11];
    float* out = (float*)d_out;

    cudaFuncSetAttribute(k_mlp, cudaFuncAttributeMaxDynamicSharedMemorySize, SMEM_TOTAL);

    k_sample<<<(MTOT + 255) / 256, 256>>>(rays_o, rays_d, dgrid, k0g, stepsize);
    k_scan<<<(N_RAYS * 32 + 255) / 256, 256>>>(viewdirs, out);
    k_h0v<<<(N_RAYS * 128) / 256, 256>>>(w0, b0);
    k_mlp<<<GRID_MLP, 256, SMEM_TOTAL>>>(w0, b0, w1, b1, w2, b2, out);
}

// round 7
// speedup vs baseline: 1.4698x; 1.0099x over previous
#include <cuda_runtime.h>
#include <cuda_fp16.h>
#include <math.h>
#include <stdint.h>

#define N_RAYS   4096
#define PSTEPS   254
#define P_INNER  231
#define MTOT     (N_RAYS*PSTEPS)      // 1,040,384
#define NTILES   (MTOT/128)           // 8128
#define WORLD    160
#define S2       (WORLD*WORLD)
#define S3       (WORLD*WORLD*WORLD)
#define ACT_SHIFT (-9.210240371976183f)
#define BG_LEN   0.2f
#define GRID_MLP 444                  // 3 CTAs per SM

// ---------------- scratch ----------------
__device__ uint16_t g_f16[MTOT*16];     // k0 features fp16 rows (12 real + 4 pad)
__device__ float    g_vembf[N_RAYS*27]; // view embedding fp32
__device__ float    g_h0v[N_RAYS*128];  // per-ray layer0 contribution of vemb + b0
__device__ float    g_alpha[MTOT];
__device__ float    g_w[MTOT];

// ---------------- helpers ----------------
__device__ __forceinline__ uint16_t f2h(float f) {
    return __half_as_ushort(__float2half_rn(f));
}
__device__ __forceinline__ uint32_t pack_h2(float f0, float f1) {   // f0 -> low half
    __half2 v = __floats2half2_rn(f0, f1);
    return *reinterpret_cast<uint32_t*>(&v);
}
__device__ __forceinline__ uint32_t smem_u32(const void* p) {
    uint32_t a;
    asm("{ .reg .u64 t; cvta.to.shared.u64 t, %1; cvt.u32.u64 %0, t; }" : "=r"(a) : "l"(p));
    return a;
}

#define LDSM_X4(r0,r1,r2,r3,addr) \
    asm volatile("ldmatrix.sync.aligned.m8n8.x4.shared.b16 {%0,%1,%2,%3}, [%4];" \
        : "=r"(r0), "=r"(r1), "=r"(r2), "=r"(r3) : "r"(addr))

#define MMA_F16(c, a0,a1,a2,a3, b0,b1) \
    asm volatile("mma.sync.aligned.m16n8k16.row.col.f32.f16.f16.f32 " \
        "{%0,%1,%2,%3}, {%4,%5,%6,%7}, {%8,%9}, {%0,%1,%2,%3};" \
        : "+f"((c)[0]), "+f"((c)[1]), "+f"((c)[2]), "+f"((c)[3]) \
        : "r"(a0), "r"(a1), "r"(a2), "r"(a3), "r"(b0), "r"(b1))

// ---------------- K1: sampling + contraction + trilinear interp ----------------
__global__ void k_sample(const float* __restrict__ ro, const float* __restrict__ rdir,
                         const float* __restrict__ dgrid, const float* __restrict__ k0g,
                         const int* __restrict__ stepsize)
{
    int s = blockIdx.x * blockDim.x + threadIdx.x;
    if (s >= MTOT) return;
    int r = s / PSTEPS;
    int p = s - r * PSTEPS;

    const float SQ3x2 = 3.4641016151377546f;
    float t;
    if (p < P_INNER) {
        t = SQ3x2 * ((float)p + 0.5f) * (1.0f / 231.0f);
    } else {
        int q = p - P_INNER;
        float L0 = 1.0f - (float)q     * (0.999f / 23.0f);
        float L1 = 1.0f - (float)(q+1) * (0.999f / 23.0f);
        t = 0.5f * SQ3x2 * (1.0f / L0 + 1.0f / L1);
    }

    float dx = rdir[r*3+0], dy = rdir[r*3+1], dz = rdir[r*3+2];
    float inv = rsqrtf(dx*dx + dy*dy + dz*dz);
    dx *= inv; dy *= inv; dz *= inv;

    float px = ro[r*3+0] + dx * t;
    float py = ro[r*3+1] + dy * t;
    float pz = ro[r*3+2] + dz * t;

    float nm = fmaxf(fabsf(px), fmaxf(fabsf(py), fabsf(pz)));
    if (nm > 1.0f) {
        float sc = (1.0f + BG_LEN - BG_LEN / nm) / nm;
        px *= sc; py *= sc; pz *= sc;
    }

    const float GS = 159.0f / 2.4f;
    float gx = fminf(fmaxf((px + 1.2f) * GS, 0.0f), 159.0f);
    float gy = fminf(fmaxf((py + 1.2f) * GS, 0.0f), 159.0f);
    float gz = fminf(fmaxf((pz + 1.2f) * GS, 0.0f), 159.0f);
    int ix = min((int)gx, 158);
    int iy = min((int)gy, 158);
    int iz = min((int)gz, 158);
    float fx = gx - (float)ix, fy = gy - (float)iy, fz = gz - (float)iz;

    int base = (ix * WORLD + iy) * WORLD + iz;
    float w00 = (1.f-fx)*(1.f-fy), w01 = (1.f-fx)*fy, w10 = fx*(1.f-fy), w11 = fx*fy;
    float wz0 = 1.f - fz, wz1 = fz;

    float wt[8];
    wt[0]=w00*wz0; wt[1]=w00*wz1; wt[2]=w01*wz0; wt[3]=w01*wz1;
    wt[4]=w10*wz0; wt[5]=w10*wz1; wt[6]=w11*wz0; wt[7]=w11*wz1;
    int off[8];
    off[0]=base;          off[1]=base+1;
    off[2]=base+WORLD;    off[3]=base+WORLD+1;
    off[4]=base+S2;       off[5]=base+S2+1;
    off[6]=base+S2+WORLD; off[7]=base+S2+WORLD+1;

    float dsum = 0.0f;
    #pragma unroll
    for (int u = 0; u < 8; u++) dsum += wt[u] * __ldg(&dgrid[off[u]]);

    int sv = *stepsize;
    float interval = (sv > 0 && sv < 1000000) ? (float)sv : __int_as_float(sv);

    float x = dsum + ACT_SHIFT;
    float sp = (x > 20.0f) ? x : log1pf(expf(x));
    g_alpha[s] = 1.0f - expf(-interval * sp);

    // k0 channels -> fp16 packed rows (12 values + 4 zero pad)
    float v[12];
    #pragma unroll
    for (int c = 0; c < 12; c++) {
        const float* gp = k0g + c * S3;
        float acc = 0.0f;
        #pragma unroll
        for (int u = 0; u < 8; u++) acc += wt[u] * __ldg(&gp[off[u]]);
        v[c] = acc;
    }
    uint32_t ph[8];
    #pragma unroll
    for (int c = 0; c < 6; c++) ph[c] = pack_h2(v[2*c], v[2*c+1]);
    ph[6] = ph[7] = 0u;
    uint4* dh = (uint4*)&g_f16[(size_t)s*16];
    dh[0] = make_uint4(ph[0],ph[1],ph[2],ph[3]);
    dh[1] = make_uint4(ph[4],ph[5],ph[6],ph[7]);
}

// ---------------- K2: warp-parallel view embedding + transmittance scan ----------------
__global__ void k_scan(const float* __restrict__ vdirs, float* __restrict__ out)
{
    int gw = (blockIdx.x * blockDim.x + threadIdx.x) >> 5;   // ray id
    int lane = threadIdx.x & 31;
    if (gw >= N_RAYS) return;

    float d0 = __ldg(&vdirs[gw*3+0]);
    float d1 = __ldg(&vdirs[gw*3+1]);
    float d2 = __ldg(&vdirs[gw*3+2]);

    if (lane < 27) {
        float v;
        if (lane < 3) {
            v = (lane == 0) ? d0 : (lane == 1) ? d1 : d2;
        } else {
            int kk = (lane < 15) ? (lane - 3) : (lane - 15);
            int c = kk >> 2, e = kk & 3;
            float dc = (c == 0) ? d0 : (c == 1) ? d1 : d2;
            float vv = dc * (float)(1 << e);
            v = (lane < 15) ? sinf(vv) : cosf(vv);
        }
        g_vembf[gw*27 + lane] = v;
    }

    float T = 1.0f;
    int base = gw * PSTEPS;
    #pragma unroll
    for (int chunk = 0; chunk < 8; chunk++) {
        int p = chunk*32 + lane;
        float a = (p < PSTEPS) ? g_alpha[base + p] : 0.0f;
        float q = 1.0f - a;
        float incl = q;
        #pragma unroll
        for (int dlt = 1; dlt < 32; dlt <<= 1) {
            float o = __shfl_up_sync(0xffffffffu, incl, dlt);
            if (lane >= dlt) incl *= o;
        }
        float excl = __shfl_up_sync(0xffffffffu, incl, 1);
        if (lane == 0) excl = 1.0f;
        if (p < PSTEPS) g_w[base + p] = a * T * excl;
        float tot = __shfl_sync(0xffffffffu, incl, 31);
        T *= tot;
    }
    if (lane == 0) {
        out[gw*3+0] = T; out[gw*3+1] = T; out[gw*3+2] = T;   // BG = 1.0
    }
}

// ---------------- K2b: per-ray layer0 view contribution: h0v = b0 + vemb @ W0[12:39] ----------------
__global__ void k_h0v(const float* __restrict__ w0, const float* __restrict__ b0)
{
    int gid = blockIdx.x * blockDim.x + threadIdx.x;
    int r = gid >> 7, n = gid & 127;
    float acc = __ldg(&b0[n]);
    #pragma unroll
    for (int k = 0; k < 27; k++)
        acc = fmaf(g_vembf[r*27 + k], __ldg(&w0[(12+k)*128 + n]), acc);
    g_h0v[r*128 + n] = acc;
}

// ---------------- K3: persistent fp16 mma.sync MLP, 128 threads, M=32/warp, 3 CTAs/SM ----------------
// smem layout (bytes)
#define SM_B1V   0                     // 128 floats
#define SM_W2    512                   // 384 floats
#define SM_A0    2048                  // double buffer: [buf][128 rows][24 fp16] = 2*6144
#define SM_B0    14336                 // [128 n][24 k] stride 48B (k 0..15 real)
#define SM_B1    20480                 // [128 n][136 k] stride 272B (k 0..127 real)
#define SMEM_TOTAL 55296

__global__ void __launch_bounds__(128, 3) k_mlp(
    const float* __restrict__ w0, const float* __restrict__ b0,
    const float* __restrict__ w1, const float* __restrict__ b1,
    const float* __restrict__ w2, const float* __restrict__ b2,
    float* __restrict__ out)
{
    extern __shared__ unsigned char smem[];
    uint32_t sb = smem_u32(smem);
    int tid = threadIdx.x;
    int w = tid >> 5, l = tid & 31;
    int g = l >> 2, tg = l & 3;

    // ---- one-time weight staging (fp16, [n][k] layout) ----
    if (tid < 128) ((float*)(smem + SM_B1V))[tid] = b1[tid];
    for (int i = tid; i < 384; i += 128) ((float*)(smem + SM_W2))[i] = w2[i];

    for (int idx = tid; idx < 128*16; idx += 128) {
        int n = idx & 127, k = idx >> 7;
        float v = (k < 12) ? w0[k*128 + n] : 0.0f;
        *(uint16_t*)(smem + SM_B0 + n*48 + k*2) = f2h(v);
    }
    for (int idx = tid; idx < 128*128; idx += 128) {
        int n = idx & 127, k = idx >> 7;
        *(uint16_t*)(smem + SM_B1 + n*272 + k*2) = f2h(w1[k*128 + n]);
    }
    float b2r0 = __ldg(&b2[0]), b2r1 = __ldg(&b2[1]), b2r2 = __ldg(&b2[2]);
    const float* b1s = (const float*)(smem + SM_B1V);
    const float* w2s = (const float*)(smem + SM_W2);

    // ---- lane-invariant ldmatrix addresses ----
    uint32_t rowA = 32u*w + (l & 7) + ((l >> 3) & 1) * 8;   // block 0; block 1 = +16 rows (768B)
    uint32_t colA = (uint32_t)(l >> 4) * 16;
    uint32_t lrow = (l & 7) + ((l >> 4) & 1) * 8;
    uint32_t lcol = ((l >> 3) & 1) * 16;
    uint32_t aB0 = sb + SM_B0 + lrow*48  + lcol;
    uint32_t aB1 = sb + SM_B1 + lrow*272 + lcol;

    int srow = tid;   // each thread stages one full row (32 B)

    // ---- prime A0 buffer 0 ----
    int m = blockIdx.x;
    if (m < NTILES) {
        const uint4* sf = (const uint4*)&g_f16[(size_t)(m*128+srow)*16];
        uint4 q0 = sf[0], q1 = sf[1];
        *(uint4*)(smem + SM_A0 + srow*48)      = q0;
        *(uint4*)(smem + SM_A0 + srow*48 + 16) = q1;
    }
    __syncthreads();
    int buf = 0;

    for (; m < NTILES; m += gridDim.x) {
        int mbase = m * 128;
        int mn = m + gridDim.x;
        bool hn = mn < NTILES;
        uint4 q0n, q1n;
        if (hn) {   // prefetch next tile rows (hidden under compute)
            const uint4* sf = (const uint4*)&g_f16[(size_t)(mn*128+srow)*16];
            q0n = sf[0]; q1n = sf[1];
        }

        // sample ids: [block][rowhalf]
        int s00 = mbase + 32*w + g;
        int s01 = s00 + 8;
        int s10 = s00 + 16;
        int s11 = s00 + 24;
        int r00 = s00 / PSTEPS, r01 = s01 / PSTEPS;
        int r10 = s10 / PSTEPS, r11 = s11 / PSTEPS;
        const float* hp[2][2] = {
            { g_h0v + (size_t)r00*128, g_h0v + (size_t)r01*128 },
            { g_h0v + (size_t)r10*128, g_h0v + (size_t)r11*128 } };

        // ---- layer 0: K=16 -> A1 frags in registers ----
        uint32_t aA = sb + SM_A0 + (uint32_t)buf*6144u + rowA*48 + colA;
        uint32_t a0f[2][4];
        LDSM_X4(a0f[0][0],a0f[0][1],a0f[0][2],a0f[0][3], aA);
        LDSM_X4(a0f[1][0],a0f[1][1],a0f[1][2],a0f[1][3], aA + 768);

        uint32_t aF[2][8][4];
        #pragma unroll
        for (int p = 0; p < 8; p++) {
            float cc[2][2][4];
            #pragma unroll
            for (int b = 0; b < 2; b++)
                #pragma unroll
                for (int hh = 0; hh < 2; hh++)
                    cc[b][hh][0]=cc[b][hh][1]=cc[b][hh][2]=cc[b][hh][3]=0.f;
            uint32_t bb0,bb1,bb2,bb3;
            LDSM_X4(bb0,bb1,bb2,bb3, aB0 + p*768);
            #pragma unroll
            for (int b = 0; b < 2; b++) {
                MMA_F16(cc[b][0], a0f[b][0],a0f[b][1],a0f[b][2],a0f[b][3], bb0,bb1);
                MMA_F16(cc[b][1], a0f[b][0],a0f[b][1],a0f[b][2],a0f[b][3], bb2,bb3);
            }
            #pragma unroll
            for (int b = 0; b < 2; b++)
                #pragma unroll
                for (int hh = 0; hh < 2; hh++) {
                    const float* c4 = cc[b][hh];
                    int col = p*16 + hh*8 + tg*2;
                    float f00 = fmaxf(c4[0] + hp[b][0][col],   0.f);
                    float f01 = fmaxf(c4[1] + hp[b][0][col+1], 0.f);
                    float f10 = fmaxf(c4[2] + hp[b][1][col],   0.f);
                    float f11 = fmaxf(c4[3] + hp[b][1][col+1], 0.f);
                    aF[b][p][0+hh*2] = pack_h2(f00, f01);
                    aF[b][p][1+hh*2] = pack_h2(f10, f11);
                }
        }

        // ---- layer 1: K=128 -> w2 partials ----
        float acc[2][2][3];
        #pragma unroll
        for (int b = 0; b < 2; b++)
            #pragma unroll
            for (int hh = 0; hh < 2; hh++)
                acc[b][hh][0]=acc[b][hh][1]=acc[b][hh][2]=0.f;

        #pragma unroll
        for (int p = 0; p < 8; p++) {
            float cc[2][2][4];
            #pragma unroll
            for (int b = 0; b < 2; b++)
                #pragma unroll
                for (int hh = 0; hh < 2; hh++)
                    cc[b][hh][0]=cc[b][hh][1]=cc[b][hh][2]=cc[b][hh][3]=0.f;
            #pragma unroll
            for (int ks = 0; ks < 8; ks++) {
                uint32_t bb0,bb1,bb2,bb3;
                LDSM_X4(bb0,bb1,bb2,bb3, aB1 + p*4352 + ks*32);
                #pragma unroll
                for (int b = 0; b < 2; b++) {
                    MMA_F16(cc[b][0], aF[b][ks][0],aF[b][ks][1],aF[b][ks][2],aF[b][ks][3], bb0,bb1);
                    MMA_F16(cc[b][1], aF[b][ks][0],aF[b][ks][1],aF[b][ks][2],aF[b][ks][3], bb2,bb3);
                }
            }
            #pragma unroll
            for (int b = 0; b < 2; b++)
                #pragma unroll
                for (int hh = 0; hh < 2; hh++) {
                    const float* c4 = cc[b][hh];
                    int col = p*16 + hh*8 + tg*2;
                    float f0 = fmaxf(c4[0] + b1s[col],   0.f);
                    float f1 = fmaxf(c4[1] + b1s[col+1], 0.f);
                    float f2 = fmaxf(c4[2] + b1s[col],   0.f);
                    float f3 = fmaxf(c4[3] + b1s[col+1], 0.f);
                    float wa0 = w2s[col*3+0],     wa1 = w2s[col*3+1],     wa2 = w2s[col*3+2];
                    float wb0 = w2s[(col+1)*3+0], wb1 = w2s[(col+1)*3+1], wb2 = w2s[(col+1)*3+2];
                    acc[b][0][0] = (hh==0) ? fmaf(f0, wa0, fmaf(f1, wb0, acc[b][0][0])) : fmaf(f0, wa0, fmaf(f1, wb0, acc[b][0][0]));
                    acc[b][0][1] = fmaf(f0, wa1, fmaf(f1, wb1, acc[b][0][1]));
                    acc[b][0][2] = fmaf(f0, wa2, fmaf(f1, wb2, acc[b][0][2]));
                    acc[b][1][0] = fmaf(f2, wa0, fmaf(f3, wb0, acc[b][1][0]));
                    acc[b][1][1] = fmaf(f2, wa1, fmaf(f3, wb1, acc[b][1][1]));
                    acc[b][1][2] = fmaf(f2, wa2, fmaf(f3, wb2, acc[b][1][2]));
                }
        }

        // ---- quad reduce + sigmoid + weighted atomic (4 samples per quad) ----
        #pragma unroll
        for (int dlt = 1; dlt <= 2; dlt <<= 1)
            #pragma unroll
            for (int b = 0; b < 2; b++)
                #pragma unroll
                for (int hh = 0; hh < 2; hh++) {
                    acc[b][hh][0] += __shfl_xor_sync(0xffffffffu, acc[b][hh][0], dlt);
                    acc[b][hh][1] += __shfl_xor_sync(0xffffffffu, acc[b][hh][1], dlt);
                    acc[b][hh][2] += __shfl_xor_sync(0xffffffffu, acc[b][hh][2], dlt);
                }
        if (tg == 0) {
            int ss[2][2] = {{s00, s01}, {s10, s11}};
            int rr[2][2] = {{r00, r01}, {r10, r11}};
            #pragma unroll
            for (int b = 0; b < 2; b++)
                #pragma unroll
                for (int hh = 0; hh < 2; hh++) {
                    float wg = g_w[ss[b][hh]];
                    float v0 = wg / (1.0f + expf(-(acc[b][hh][0] + b2r0)));
                    float v1 = wg / (1.0f + expf(-(acc[b][hh][1] + b2r1)));
                    float v2 = wg / (1.0f + expf(-(acc[b][hh][2] + b2r2)));
                    atomicAdd(&out[rr[b][hh]*3+0], v0);
                    atomicAdd(&out[rr[b][hh]*3+1], v1);
                    atomicAdd(&out[rr[b][hh]*3+2], v2);
                }
        }

        // ---- stage next tile into alternate buffer ----
        if (hn) {
            uint32_t ab = SM_A0 + (uint32_t)(buf^1)*6144u;
            *(uint4*)(smem + ab + srow*48)      = q0n;
            *(uint4*)(smem + ab + srow*48 + 16) = q1n;
        }
        __syncthreads();
        buf ^= 1;
    }
}

// ---------------- launcher ----------------
extern "C" void kernel_launch(void* const* d_in, const int* in_sizes, int n_in,
                              void* d_out, int out_size)
{
    const float* rays_o   = (const float*)d_in[0];
    const float* rays_d   = (const float*)d_in[1];
    const float* viewdirs = (const float*)d_in[2];
    const float* dgrid    = (const float*)d_in[3];
    const float* k0g      = (const float*)d_in[4];
    const float* w0 = (const float*)d_in[5];
    const float* b0 = (const float*)d_in[6];
    const float* w1 = (const float*)d_in[7];
    const float* b1 = (const float*)d_in[8];
    const float* w2 = (const float*)d_in[9];
    const float* b2 = (const float*)d_in[10];
    const int* stepsize = (const int*)d_in[11];
    float* out = (float*)d_out;

    cudaFuncSetAttribute(k_mlp, cudaFuncAttributeMaxDynamicSharedMemorySize, SMEM_TOTAL);

    k_sample<<<(MTOT + 255) / 256, 256>>>(rays_o, rays_d, dgrid, k0g, stepsize);
    k_scan<<<(N_RAYS * 32 + 255) / 256, 256>>>(viewdirs, out);
    k_h0v<<<(N_RAYS * 128) / 256, 256>>>(w0, b0);
    k_mlp<<<GRID_MLP, 128, SMEM_TOTAL>>>(w0, b0, w1, b1, w2, b2, out);
}

// round 8
// speedup vs baseline: 1.7347x; 1.1802x over previous
#include <cuda_runtime.h>
#include <cuda_fp16.h>
#include <math.h>
#include <stdint.h>

#define N_RAYS   4096
#define PSTEPS   254
#define P_INNER  231
#define MTOT     (N_RAYS*PSTEPS)      // 1,040,384
#define NTILES   (MTOT/128)           // 8128
#define WORLD    160
#define S2       (WORLD*WORLD)
#define S3       (WORLD*WORLD*WORLD)
#define ACT_SHIFT (-9.210240371976183f)
#define BG_LEN   0.2f
#define GRID_MLP 444                  // 3 CTAs per SM

// ---------------- scratch ----------------
__device__ uint4    g_pack[S3*2];       // per-voxel record: 12 fp16 k0 + fp32 density + pad (32 B)
__device__ uint16_t g_f16[MTOT*16];     // k0 features fp16 rows (12 real + 4 pad)
__device__ float    g_vembf[N_RAYS*27]; // view embedding fp32
__device__ float    g_h0v[N_RAYS*128];  // per-ray layer0 contribution of vemb + b0
__device__ float    g_alpha[MTOT];
__device__ float    g_w[MTOT];

// ---------------- helpers ----------------
__device__ __forceinline__ uint16_t f2h(float f) {
    return __half_as_ushort(__float2half_rn(f));
}
__device__ __forceinline__ uint32_t pack_h2(float f0, float f1) {   // f0 -> low half
    __half2 v = __floats2half2_rn(f0, f1);
    return *reinterpret_cast<uint32_t*>(&v);
}
__device__ __forceinline__ uint32_t smem_u32(const void* p) {
    uint32_t a;
    asm("{ .reg .u64 t; cvta.to.shared.u64 t, %1; cvt.u32.u64 %0, t; }" : "=r"(a) : "l"(p));
    return a;
}

#define LDSM_X4(r0,r1,r2,r3,addr) \
    asm volatile("ldmatrix.sync.aligned.m8n8.x4.shared.b16 {%0,%1,%2,%3}, [%4];" \
        : "=r"(r0), "=r"(r1), "=r"(r2), "=r"(r3) : "r"(addr))

#define LDSM_X2(r0,r1,addr) \
    asm volatile("ldmatrix.sync.aligned.m8n8.x2.shared.b16 {%0,%1}, [%2];" \
        : "=r"(r0), "=r"(r1) : "r"(addr))

#define MMA_F16(c, a0,a1,a2,a3, b0,b1) \
    asm volatile("mma.sync.aligned.m16n8k16.row.col.f32.f16.f16.f32 " \
        "{%0,%1,%2,%3}, {%4,%5,%6,%7}, {%8,%9}, {%0,%1,%2,%3};" \
        : "+f"((c)[0]), "+f"((c)[1]), "+f"((c)[2]), "+f"((c)[3]) \
        : "r"(a0), "r"(a1), "r"(a2), "r"(a3), "r"(b0), "r"(b1))

// ---------------- K0: grid repack (channel-interleaved 32B records) ----------------
__global__ void k_pack(const float* __restrict__ dgrid, const float* __restrict__ k0g)
{
    int idx = blockIdx.x * blockDim.x + threadIdx.x;
    if (idx >= S3) return;
    uint32_t h[6];
    #pragma unroll
    for (int c = 0; c < 6; c++)
        h[c] = pack_h2(__ldg(&k0g[(2*c)*S3 + idx]), __ldg(&k0g[(2*c+1)*S3 + idx]));
    float d = __ldg(&dgrid[idx]);
    g_pack[(size_t)idx*2+0] = make_uint4(h[0], h[1], h[2], h[3]);
    g_pack[(size_t)idx*2+1] = make_uint4(h[4], h[5], __float_as_uint(d), 0u);
}

// ---------------- K1: sampling + contraction + trilinear interp (packed reads) ----------------
__global__ void k_sample(const float* __restrict__ ro, const float* __restrict__ rdir,
                         const int* __restrict__ stepsize)
{
    int s = blockIdx.x * blockDim.x + threadIdx.x;
    if (s >= MTOT) return;
    int r = s / PSTEPS;
    int p = s - r * PSTEPS;

    const float SQ3x2 = 3.4641016151377546f;
    float t;
    if (p < P_INNER) {
        t = SQ3x2 * ((float)p + 0.5f) * (1.0f / 231.0f);
    } else {
        int q = p - P_INNER;
        float L0 = 1.0f - (float)q     * (0.999f / 23.0f);
        float L1 = 1.0f - (float)(q+1) * (0.999f / 23.0f);
        t = 0.5f * SQ3x2 * (1.0f / L0 + 1.0f / L1);
    }

    float dx = rdir[r*3+0], dy = rdir[r*3+1], dz = rdir[r*3+2];
    float inv = rsqrtf(dx*dx + dy*dy + dz*dz);
    dx *= inv; dy *= inv; dz *= inv;

    float px = ro[r*3+0] + dx * t;
    float py = ro[r*3+1] + dy * t;
    float pz = ro[r*3+2] + dz * t;

    float nm = fmaxf(fabsf(px), fmaxf(fabsf(py), fabsf(pz)));
    if (nm > 1.0f) {
        float sc = (1.0f + BG_LEN - BG_LEN / nm) / nm;
        px *= sc; py *= sc; pz *= sc;
    }

    const float GS = 159.0f / 2.4f;
    float gx = fminf(fmaxf((px + 1.2f) * GS, 0.0f), 159.0f);
    float gy = fminf(fmaxf((py + 1.2f) * GS, 0.0f), 159.0f);
    float gz = fminf(fmaxf((pz + 1.2f) * GS, 0.0f), 159.0f);
    int ix = min((int)gx, 158);
    int iy = min((int)gy, 158);
    int iz = min((int)gz, 158);
    float fx = gx - (float)ix, fy = gy - (float)iy, fz = gz - (float)iz;

    int base = (ix * WORLD + iy) * WORLD + iz;
    float w00 = (1.f-fx)*(1.f-fy), w01 = (1.f-fx)*fy, w10 = fx*(1.f-fy), w11 = fx*fy;
    float wz0 = 1.f - fz, wz1 = fz;

    float wt[8];
    wt[0]=w00*wz0; wt[1]=w00*wz1; wt[2]=w01*wz0; wt[3]=w01*wz1;
    wt[4]=w10*wz0; wt[5]=w10*wz1; wt[6]=w11*wz0; wt[7]=w11*wz1;
    int off[8];
    off[0]=base;          off[1]=base+1;
    off[2]=base+WORLD;    off[3]=base+WORLD+1;
    off[4]=base+S2;       off[5]=base+S2+1;
    off[6]=base+S2+WORLD; off[7]=base+S2+WORLD+1;

    float acc[12];
    #pragma unroll
    for (int c = 0; c < 12; c++) acc[c] = 0.0f;
    float dsum = 0.0f;

    #pragma unroll
    for (int u = 0; u < 8; u++) {
        const uint4* rec = &g_pack[(size_t)off[u]*2];
        uint4 qa = __ldg(&rec[0]);
        uint4 qb = __ldg(&rec[1]);
        float wtu = wt[u];
        float2 f;
        f = __half22float2(*(const __half2*)&qa.x); acc[0] += wtu*f.x; acc[1] += wtu*f.y;
        f = __half22float2(*(const __half2*)&qa.y); acc[2] += wtu*f.x; acc[3] += wtu*f.y;
        f = __half22float2(*(const __half2*)&qa.z); acc[4] += wtu*f.x; acc[5] += wtu*f.y;
        f = __half22float2(*(const __half2*)&qa.w); acc[6] += wtu*f.x; acc[7] += wtu*f.y;
        f = __half22float2(*(const __half2*)&qb.x); acc[8] += wtu*f.x; acc[9] += wtu*f.y;
        f = __half22float2(*(const __half2*)&qb.y); acc[10]+= wtu*f.x; acc[11]+= wtu*f.y;
        dsum += wtu * __uint_as_float(qb.z);
    }

    int sv = *stepsize;
    float interval = (sv > 0 && sv < 1000000) ? (float)sv : __int_as_float(sv);

    float x = dsum + ACT_SHIFT;
    float sp = (x > 20.0f) ? x : log1pf(expf(x));
    g_alpha[s] = 1.0f - expf(-interval * sp);

    uint32_t ph[8];
    #pragma unroll
    for (int c = 0; c < 6; c++) ph[c] = pack_h2(acc[2*c], acc[2*c+1]);
    ph[6] = ph[7] = 0u;
    uint4* dh = (uint4*)&g_f16[(size_t)s*16];
    dh[0] = make_uint4(ph[0],ph[1],ph[2],ph[3]);
    dh[1] = make_uint4(ph[4],ph[5],ph[6],ph[7]);
}

// ---------------- K2: warp-parallel view embedding + transmittance scan ----------------
__global__ void k_scan(const float* __restrict__ vdirs, float* __restrict__ out)
{
    int gw = (blockIdx.x * blockDim.x + threadIdx.x) >> 5;   // ray id
    int lane = threadIdx.x & 31;
    if (gw >= N_RAYS) return;

    float d0 = __ldg(&vdirs[gw*3+0]);
    float d1 = __ldg(&vdirs[gw*3+1]);
    float d2 = __ldg(&vdirs[gw*3+2]);

    if (lane < 27) {
        float v;
        if (lane < 3) {
            v = (lane == 0) ? d0 : (lane == 1) ? d1 : d2;
        } else {
            int kk = (lane < 15) ? (lane - 3) : (lane - 15);
            int c = kk >> 2, e = kk & 3;
            float dc = (c == 0) ? d0 : (c == 1) ? d1 : d2;
            float vv = dc * (float)(1 << e);
            v = (lane < 15) ? sinf(vv) : cosf(vv);
        }
        g_vembf[gw*27 + lane] = v;
    }

    float T = 1.0f;
    int base = gw * PSTEPS;
    #pragma unroll
    for (int chunk = 0; chunk < 8; chunk++) {
        int p = chunk*32 + lane;
        float a = (p < PSTEPS) ? g_alpha[base + p] : 0.0f;
        float q = 1.0f - a;
        float incl = q;
        #pragma unroll
        for (int dlt = 1; dlt < 32; dlt <<= 1) {
            float o = __shfl_up_sync(0xffffffffu, incl, dlt);
            if (lane >= dlt) incl *= o;
        }
        float excl = __shfl_up_sync(0xffffffffu, incl, 1);
        if (lane == 0) excl = 1.0f;
        if (p < PSTEPS) g_w[base + p] = a * T * excl;
        float tot = __shfl_sync(0xffffffffu, incl, 31);
        T *= tot;
    }
    if (lane == 0) {
        out[gw*3+0] = T; out[gw*3+1] = T; out[gw*3+2] = T;   // BG = 1.0
    }
}

// ---------------- K2b: per-ray layer0 view contribution: h0v = b0 + vemb @ W0[12:39] ----------------
__global__ void k_h0v(const float* __restrict__ w0, const float* __restrict__ b0)
{
    int gid = blockIdx.x * blockDim.x + threadIdx.x;
    int r = gid >> 7, n = gid & 127;
    float acc = __ldg(&b0[n]);
    #pragma unroll
    for (int k = 0; k < 27; k++)
        acc = fmaf(g_vembf[r*27 + k], __ldg(&w0[(12+k)*128 + n]), acc);
    g_h0v[r*128 + n] = acc;
}

// ---------------- K3: persistent fp16 mma.sync MLP (layer2 as MMA), 128 thr, 3 CTAs/SM ----------------
// smem layout (bytes)
#define SM_B1V   0                     // 128 floats
#define SM_H0    1024                  // double buffer: [buf][2 rays][128 floats] = 2*1024
#define SM_A0    3072                  // double buffer: [buf][128 rows][24 fp16] = 2*6144
#define SM_B0    15360                 // [128 n][24 k] stride 48B (k 0..15 real)
#define SM_B1    21504                 // [128 n][136 k] stride 272B (k 0..127 real)
#define SM_B2    56320                 // [8 n][136 k] stride 272B (n 0..2 real)
#define SMEM_TOTAL 58496

__global__ void __launch_bounds__(128, 3) k_mlp(
    const float* __restrict__ w0, const float* __restrict__ b0,
    const float* __restrict__ w1, const float* __restrict__ b1,
    const float* __restrict__ w2, const float* __restrict__ b2,
    float* __restrict__ out)
{
    extern __shared__ unsigned char smem[];
    uint32_t sb = smem_u32(smem);
    int tid = threadIdx.x;
    int w = tid >> 5, l = tid & 31;
    int g = l >> 2, tg = l & 3;

    // ---- one-time weight staging (fp16, [n][k] layout) ----
    if (tid < 128) ((float*)(smem + SM_B1V))[tid] = b1[tid];

    for (int idx = tid; idx < 128*16; idx += 128) {
        int n = idx & 127, k = idx >> 7;
        float v = (k < 12) ? w0[k*128 + n] : 0.0f;
        *(uint16_t*)(smem + SM_B0 + n*48 + k*2) = f2h(v);
    }
    for (int idx = tid; idx < 128*128; idx += 128) {
        int n = idx & 127, k = idx >> 7;
        *(uint16_t*)(smem + SM_B1 + n*272 + k*2) = f2h(w1[k*128 + n]);
    }
    for (int idx = tid; idx < 8*128; idx += 128) {
        int n = idx & 7, k = idx >> 3;
        float v = (n < 3) ? w2[k*3 + n] : 0.0f;
        *(uint16_t*)(smem + SM_B2 + n*272 + k*2) = f2h(v);
    }
    float b2r0 = __ldg(&b2[0]), b2r1 = __ldg(&b2[1]), b2r2 = __ldg(&b2[2]);
    const float* b1s = (const float*)(smem + SM_B1V);

    // ---- lane-invariant ldmatrix addresses ----
    uint32_t rowA = 32u*w + (l & 7) + ((l >> 3) & 1) * 8;   // block 0; block 1 = +16 rows (768B)
    uint32_t colA = (uint32_t)(l >> 4) * 16;
    uint32_t lrow = (l & 7) + ((l >> 4) & 1) * 8;
    uint32_t lcol = ((l >> 3) & 1) * 16;
    uint32_t aB0 = sb + SM_B0 + lrow*48  + lcol;
    uint32_t aB1 = sb + SM_B1 + lrow*272 + lcol;
    uint32_t aB2 = sb + SM_B2 + (uint32_t)(l & 7)*272 + ((l >> 3) & 1)*16;

    int srow = tid;   // each thread stages one full row (32 B)

    // ---- prime A0 + H0 buffer 0 ----
    int m = blockIdx.x;
    if (m < NTILES) {
        const uint4* sf = (const uint4*)&g_f16[(size_t)(m*128+srow)*16];
        uint4 q0 = sf[0], q1 = sf[1];
        *(uint4*)(smem + SM_A0 + srow*48)      = q0;
        *(uint4*)(smem + SM_A0 + srow*48 + 16) = q1;
        int rA = (m*128) / PSTEPS;
        int rB = (m*128 + 127) / PSTEPS;
        float* hs = (float*)(smem + SM_H0);
        hs[tid]       = g_h0v[(size_t)rA*128 + tid];
        hs[128 + tid] = g_h0v[(size_t)rB*128 + tid];
    }
    __syncthreads();

    // ---- preload layer-2 B fragments (tile-invariant) ----
    uint32_t b2f[8][2];
    #pragma unroll
    for (int p = 0; p < 8; p++) LDSM_X2(b2f[p][0], b2f[p][1], aB2 + p*32);

    int buf = 0;

    for (; m < NTILES; m += gridDim.x) {
        int mbase = m * 128;
        int mn = m + gridDim.x;
        bool hn = mn < NTILES;
        uint4 q0n, q1n;
        if (hn) {   // prefetch next tile rows (hidden under compute)
            const uint4* sf = (const uint4*)&g_f16[(size_t)(mn*128+srow)*16];
            q0n = sf[0]; q1n = sf[1];
        }

        // sample ids: [block][rowhalf]
        int s00 = mbase + 32*w + g;
        int s01 = s00 + 8;
        int s10 = s00 + 16;
        int s11 = s00 + 24;
        int r00 = s00 / PSTEPS, r01 = s01 / PSTEPS;
        int r10 = s10 / PSTEPS, r11 = s11 / PSTEPS;
        int rAc = mbase / PSTEPS;
        const float* h0sb = (const float*)(smem + SM_H0 + (uint32_t)buf*1024u);
        const float* hp[2][2] = {
            { h0sb + ((r00 != rAc) ? 128 : 0), h0sb + ((r01 != rAc) ? 128 : 0) },
            { h0sb + ((r10 != rAc) ? 128 : 0), h0sb + ((r11 != rAc) ? 128 : 0) } };

        // ---- layer 0: K=16 -> A1 frags in registers ----
        uint32_t aA = sb + SM_A0 + (uint32_t)buf*6144u + rowA*48 + colA;
        uint32_t a0f[2][4];
        LDSM_X4(a0f[0][0],a0f[0][1],a0f[0][2],a0f[0][3], aA);
        LDSM_X4(a0f[1][0],a0f[1][1],a0f[1][2],a0f[1][3], aA + 768);

        uint32_t aF[2][8][4];
        #pragma unroll
        for (int p = 0; p < 8; p++) {
            float cc[2][2][4];
            #pragma unroll
            for (int b = 0; b < 2; b++)
                #pragma unroll
                for (int hh = 0; hh < 2; hh++)
                    cc[b][hh][0]=cc[b][hh][1]=cc[b][hh][2]=cc[b][hh][3]=0.f;
            uint32_t bb0,bb1,bb2,bb3;
            LDSM_X4(bb0,bb1,bb2,bb3, aB0 + p*768);
            #pragma unroll
            for (int b = 0; b < 2; b++) {
                MMA_F16(cc[b][0], a0f[b][0],a0f[b][1],a0f[b][2],a0f[b][3], bb0,bb1);
                MMA_F16(cc[b][1], a0f[b][0],a0f[b][1],a0f[b][2],a0f[b][3], bb2,bb3);
            }
            #pragma unroll
            for (int b = 0; b < 2; b++)
                #pragma unroll
                for (int hh = 0; hh < 2; hh++) {
                    const float* c4 = cc[b][hh];
                    int col = p*16 + hh*8 + tg*2;
                    float2 hA = *(const float2*)&hp[b][0][col];
                    float2 hB = *(const float2*)&hp[b][1][col];
                    float f00 = fmaxf(c4[0] + hA.x, 0.f);
                    float f01 = fmaxf(c4[1] + hA.y, 0.f);
                    float f10 = fmaxf(c4[2] + hB.x, 0.f);
                    float f11 = fmaxf(c4[3] + hB.y, 0.f);
                    aF[b][p][0+hh*2] = pack_h2(f00, f01);
                    aF[b][p][1+hh*2] = pack_h2(f10, f11);
                }
        }

        // ---- layer 1 (K=128) + fused layer 2 MMA per 16-col chunk ----
        float c2[2][4];
        c2[0][0]=c2[0][1]=c2[0][2]=c2[0][3]=0.f;
        c2[1][0]=c2[1][1]=c2[1][2]=c2[1][3]=0.f;

        #pragma unroll
        for (int p = 0; p < 8; p++) {
            float cc[2][2][4];
            #pragma unroll
            for (int b = 0; b < 2; b++)
                #pragma unroll
                for (int hh = 0; hh < 2; hh++)
                    cc[b][hh][0]=cc[b][hh][1]=cc[b][hh][2]=cc[b][hh][3]=0.f;
            #pragma unroll
            for (int ks = 0; ks < 8; ks++) {
                uint32_t bb0,bb1,bb2,bb3;
                LDSM_X4(bb0,bb1,bb2,bb3, aB1 + p*4352 + ks*32);
                #pragma unroll
                for (int b = 0; b < 2; b++) {
                    MMA_F16(cc[b][0], aF[b][ks][0],aF[b][ks][1],aF[b][ks][2],aF[b][ks][3], bb0,bb1);
                    MMA_F16(cc[b][1], aF[b][ks][0],aF[b][ks][1],aF[b][ks][2],aF[b][ks][3], bb2,bb3);
                }
            }
            // bias + relu + pack -> layer2 A frag; accumulate layer2 MMA (k-chunk = p)
            #pragma unroll
            for (int b = 0; b < 2; b++) {
                uint32_t hf[4];
                #pragma unroll
                for (int hh = 0; hh < 2; hh++) {
                    const float* c4 = cc[b][hh];
                    int col = p*16 + hh*8 + tg*2;
                    float f0 = fmaxf(c4[0] + b1s[col],   0.f);
                    float f1 = fmaxf(c4[1] + b1s[col+1], 0.f);
                    float f2 = fmaxf(c4[2] + b1s[col],   0.f);
                    float f3 = fmaxf(c4[3] + b1s[col+1], 0.f);
                    hf[0+hh*2] = pack_h2(f0, f1);
                    hf[1+hh*2] = pack_h2(f2, f3);
                }
                MMA_F16(c2[b], hf[0],hf[1],hf[2],hf[3], b2f[p][0], b2f[p][1]);
            }
        }

        // ---- epilogue: sigmoid + weighted atomic, direct from c2 fragments ----
        if (tg == 0) {
            #pragma unroll
            for (int b = 0; b < 2; b++) {
                int sA = (b == 0) ? s00 : s10;
                int sB = (b == 0) ? s01 : s11;
                int rA_ = (b == 0) ? r00 : r10;
                int rB_ = (b == 0) ? r01 : r11;
                float wgA = g_w[sA], wgB = g_w[sB];
                atomicAdd(&out[rA_*3+0], wgA / (1.0f + __expf(-(c2[b][0] + b2r0))));
                atomicAdd(&out[rA_*3+1], wgA / (1.0f + __expf(-(c2[b][1] + b2r1))));
                atomicAdd(&out[rB_*3+0], wgB / (1.0f + __expf(-(c2[b][2] + b2r0))));
                atomicAdd(&out[rB_*3+1], wgB / (1.0f + __expf(-(c2[b][3] + b2r1))));
            }
        } else if (tg == 1) {
            #pragma unroll
            for (int b = 0; b < 2; b++) {
                int sA = (b == 0) ? s00 : s10;
                int sB = (b == 0) ? s01 : s11;
                int rA_ = (b == 0) ? r00 : r10;
                int rB_ = (b == 0) ? r01 : r11;
                float wgA = g_w[sA], wgB = g_w[sB];
                atomicAdd(&out[rA_*3+2], wgA / (1.0f + __expf(-(c2[b][0] + b2r2))));
                atomicAdd(&out[rB_*3+2], wgB / (1.0f + __expf(-(c2[b][2] + b2r2))));
            }
        }

        // ---- stage next tile (A0 + H0) into alternate buffer ----
        if (hn) {
            uint32_t ab = SM_A0 + (uint32_t)(buf^1)*6144u;
            *(uint4*)(smem + ab + srow*48)      = q0n;
            *(uint4*)(smem + ab + srow*48 + 16) = q1n;
            int rAn = (mn*128) / PSTEPS;
            int rBn = (mn*128 + 127) / PSTEPS;
            float* hs = (float*)(smem + SM_H0 + (uint32_t)(buf^1)*1024u);
            hs[tid]       = g_h0v[(size_t)rAn*128 + tid];
            hs[128 + tid] = g_h0v[(size_t)rBn*128 + tid];
        }
        __syncthreads();
        buf ^= 1;
    }
}

// ---------------- launcher ----------------
extern "C" void kernel_launch(void* const* d_in, const int* in_sizes, int n_in,
                              void* d_out, int out_size)
{
    const float* rays_o   = (const float*)d_in[0];
    const float* rays_d   = (const float*)d_in[1];
    const float* viewdirs = (const float*)d_in[2];
    const float* dgrid    = (const float*)d_in[3];
    const float* k0g      = (const float*)d_in[4];
    const float* w0 = (const float*)d_in[5];
    const float* b0 = (const float*)d_in[6];
    const float* w1 = (const float*)d_in[7];
    const float* b1 = (const float*)d_in[8];
    const float* w2 = (const float*)d_in[9];
    const float* b2 = (const float*)d_in[10];
    const int* stepsize = (const int*)d_in[11];
    float* out = (float*)d_out;

    cudaFuncSetAttribute(k_mlp, cudaFuncAttributeMaxDynamicSharedMemorySize, SMEM_TOTAL);

    k_pack<<<(S3 + 255) / 256, 256>>>(dgrid, k0g);
    k_sample<<<(MTOT + 255) / 256, 256>>>(rays_o, rays_d, stepsize);
    k_scan<<<(N_RAYS * 32 + 255) / 256, 256>>>(viewdirs, out);
    k_h0v<<<(N_RAYS * 128) / 256, 256>>>(w0, b0);
    k_mlp<<<GRID_MLP, 128, SMEM_TOTAL>>>(w0, b0, w1, b1, w2, b2, out);
}